// round 7
// baseline (speedup 1.0000x reference)
#include <cuda_runtime.h>

// Decoder: 8 batches of 32-segment piecewise-linear functions sampled at
// 196608 uniform points. Output [8, 196608] fp32 = 6.29MB (L2-resident).
// Barrier-free, smem-free. Per-warp register knot table via shuffle scan;
// ballot-based O(1) segment search; branchless 7-op/pixel hot loop.

#define S_TOTAL 196608
#define NB 8
#define NSEG 32
#define NP1 33
#define THREADS 256
#define WARPS (THREADS / 32)                        // 8
#define ITERS 4                                     // float4s per thread
#define PIX_PER_WARP (32 * ITERS * 4)               // 512 contiguous pixels
#define PIX_PER_BLOCK (WARPS * PIX_PER_WARP)        // 4096
#define BLOCKS_PER_BATCH (S_TOTAL / PIX_PER_BLOCK)  // 48
#define FULLMASK 0xffffffffu

__global__ __launch_bounds__(THREADS) void decoder_pwl_kernel(
    const float* __restrict__ segx,
    const float* __restrict__ segy,
    float* __restrict__ out)
{
    const int b = blockIdx.x / BLOCKS_PER_BATCH;
    const int chunk = blockIdx.x - b * BLOCKS_PER_BATCH;
    const int w = threadIdx.x >> 5;
    const int lane = threadIdx.x & 31;
    const float inv = 1.0f / (float)S_TOTAL;        // <=1ulp vs IEEE div; tol 1e-3

    // ---- Per-warp register-resident knot table (no smem, no barriers) ----
    // Running-max scan over 33 knots, ties -> later entry wins.
    const float* px = segx + b * NP1;
    const float* py = segy + b * NP1;
    const float x0v = px[0];                         // uniform LDG, broadcast
    const float y0v = py[0];
    float xv = px[lane + 1];
    float yv = py[lane + 1];
    #pragma unroll
    for (int d = 1; d < 32; d <<= 1) {
        float ox = __shfl_up_sync(FULLMASK, xv, d);
        float oy = __shfl_up_sync(FULLMASK, yv, d);
        if (lane >= d && ox > xv) { xv = ox; yv = oy; }
    }
    if (x0v > xv) { xv = x0v; yv = y0v; }            // fold in knot 0 as prefix
    float xp = __shfl_up_sync(FULLMASK, xv, 1);      // lane l: knot X[l]
    float yp = __shfl_up_sync(FULLMASK, yv, 1);      // lane l: Y[l]
    if (lane == 0) { xp = x0v; yp = y0v; }
    float dd = xv - xp;
    if (dd == 0.0f) dd = 0.0001f;
    const float rs = (yv - yp) / dd;                 // lane l: slope of seg l

    // ---- Warp tile: contiguous 512 pixels ----
    const int sw = chunk * PIX_PER_BLOCK + w * PIX_PER_WARP;  // first pixel
    const float x_lo = (float)(sw + 1) * inv;
    const float x_hi = (float)(sw + PIX_PER_WARP) * inv;

    // Ballot search: X[] is non-decreasing across lanes, so the <= predicate
    // forms a prefix mask; j = position of highest set bit. mask==0 (x below
    // first knot) clamps to segment 0, matching the reference's lower clamp;
    // bit31 set gives segment 31, matching the upper clamp.
    const unsigned mlo = __ballot_sync(FULLMASK, xp <= x_lo);
    const unsigned mhi = __ballot_sync(FULLMASK, xp <= x_hi);
    const int jl = max(31 - __clz(mlo), 0);
    const int jh = max(31 - __clz(mhi), 0);

    const float xbase = (float)(sw + lane * 4 + 1) * inv;   // thread's pixel 0
    float4* out4 = reinterpret_cast<float4*>(out);
    const int obase = b * (S_TOTAL / 4) + (sw >> 2) + lane;

    if (jh <= jl + 1) {
        // Common case (>99.5% of warps): at most one knot boundary in tile.
        const float xb  = __shfl_sync(FULLMASK, xp, jh);
        const float c0x = __shfl_sync(FULLMASK, xp, jl);
        const float c0y = __shfl_sync(FULLMASK, yp, jl);
        const float c0r = __shfl_sync(FULLMASK, rs, jl);
        const float c1y = __shfl_sync(FULLMASK, yp, jh);
        const float c1r = __shfl_sync(FULLMASK, rs, jh);
        #pragma unroll
        for (int i = 0; i < ITERS; i++) {
            float4 o;
            float* ov = &o.x;
            #pragma unroll
            for (int e = 0; e < 4; e++) {
                float xin = xbase + (float)(i * 128 + e) * inv;  // const-folded
                bool hi = (xin >= xb);
                float cx = hi ? xb  : c0x;
                float cy = hi ? c1y : c0y;
                float cr = hi ? c1r : c0r;
                ov[e] = fmaf(cr, xin - cx, cy);      // same arith order as ref
            }
            out4[obase + i * 32] = o;
        }
    } else {
        // Rare (~0.3% of warps, warp-uniform): per-pixel shuffle search.
        #pragma unroll
        for (int i = 0; i < ITERS; i++) {
            float4 o;
            float* ov = &o.x;
            #pragma unroll
            for (int e = 0; e < 4; e++) {
                float xin = xbase + (float)(i * 128 + e) * inv;
                int j = 0;
                #pragma unroll
                for (int st = 16; st >= 1; st >>= 1) {
                    float xc = __shfl_sync(FULLMASK, xp, j + st);  // per-lane src
                    if (xc <= xin) j += st;
                }
                float cx = __shfl_sync(FULLMASK, xp, j);
                float cy = __shfl_sync(FULLMASK, yp, j);
                float cr = __shfl_sync(FULLMASK, rs, j);
                ov[e] = fmaf(cr, xin - cx, cy);
            }
            out4[obase + i * 32] = o;
        }
    }
}

extern "C" void kernel_launch(void* const* d_in, const int* in_sizes, int n_in,
                              void* d_out, int out_size) {
    const float* segx = (const float*)d_in[0];
    const float* segy = (const float*)d_in[1];
    float* out = (float*)d_out;

    const int blocks = NB * BLOCKS_PER_BATCH;        // 384
    decoder_pwl_kernel<<<blocks, THREADS>>>(segx, segy, out);
}